// round 11
// baseline (speedup 1.0000x reference)
#include <cuda_runtime.h>

// SimpleSNN: T=500 sequential steps, B=2048, 12 -> 38 (RLeaky) -> 7 (Leaky)
// Outputs flat: spk1[T,B,38], mem1[T,B,38], spk2[T,B,7], mem2[T,B,7]
//
// Round-batched pipeline (G=4 steps per __syncthreads), register x prefetch,
// ballot-bitmask spk1 publication (round-10 design), with ONE change:
// NB=2 batches per 128-thread block -> 1024 blocks -> 7 blocks/SM, 27.7
// warps/SM (occupancy was grid-limited at 512 blocks). launch_bounds(128,7)
// guarantees regs <= 73 so the full grid is resident in a single wave.

#define T_STEPS  500
#define BATCH    2048
#define NIN      12
#define NL1      38
#define NL2      7
#define NB       2              // batch elements per block
#define NTHREADS 128
#define PROD_T   96             // warps 0-2 run the L1 step body (ballot)
#define L1_T     (NB*NL1)       // 76 real L1 threads
#define L2_BASE  96             // L2 = warp 3
#define L2_T     (NB*NL2)       // 14
#define X_T      (NB*NIN)       // 24
#define W2STRIDE 44             // padded W2 row stride (conflict-free broadcast)
#define GSTEP    4              // steps per round
#define NSLOT    8              // ring depth (2 rounds)

__global__ __launch_bounds__(NTHREADS, 7)
void snn_scan_kernel(const float* __restrict__ x,
                     const float* __restrict__ W1,
                     const float* __restrict__ V,
                     const float* __restrict__ W2,
                     const float* __restrict__ pb1,
                     const float* __restrict__ pb2,
                     const float* __restrict__ pth,
                     float* __restrict__ out)
{
    __shared__ float    xsh[NSLOT][X_T];   // x ring: one slot per step
    __shared__ unsigned sbit[NSLOT][4];    // spike bitmask ring: 3 words used/slot
    __shared__ float    w2sh[NL2 * W2STRIDE];

    const int tid  = threadIdx.x;
    const int wid  = tid >> 5;
    const int b0   = blockIdx.x * NB;
    const float thr = *pth;

    const size_t stepx = (size_t)BATCH * NIN;
    const size_t step1 = (size_t)BATCH * NL1;
    const size_t step2 = (size_t)BATCH * NL2;

    // ---- one-time shared init ----
    for (int i = tid; i < NL2 * W2STRIDE; i += NTHREADS) {
        int k = i / W2STRIDE;
        int j = i - k * W2STRIDE;
        w2sh[i] = (j < NL1) ? W2[k * NL1 + j] : 0.0f;
    }

    const bool isP  = (tid < PROD_T);   // runs L1 step body (incl. ballot)
    const bool isL1 = (tid < L1_T);     // real L1 neuron
    const bool isX  = (tid < X_T);
    const bool isL2 = (tid >= L2_BASE) && (tid < L2_BASE + L2_T);

    // ---- layer 1 per-thread state ----
    const float beta1 = *pb1;
    float w1r[NIN];
    float vj = 0.f, mem1 = 0.f, spk1 = 0.f;
    int xoff = 0;
    float *pS1 = out, *pM1 = out;
    if (isL1) {
        int bl = tid / NL1, j = tid - bl * NL1;
        #pragma unroll
        for (int i = 0; i < NIN; ++i) w1r[i] = W1[j * NIN + i];
        vj   = V[j];
        xoff = bl * NIN;
        size_t o = (size_t)(b0 + bl) * NL1 + j;
        pS1 = out + o;
        pM1 = out + (size_t)T_STEPS * BATCH * NL1 + o;
    } else {
        #pragma unroll
        for (int i = 0; i < NIN; ++i) w1r[i] = 0.f;  // ballast lanes: defined math
    }

    // ---- layer 2 per-thread state ----
    const float beta2 = *pb2;
    float mem2 = 0.f;
    int w0i = 0, offi = 0;
    const float4* w2v = (const float4*)w2sh;
    float *pS2 = out, *pM2 = out;
    if (isL2) {
        int t2 = tid - L2_BASE;
        int bl = t2 / NL2, k = t2 - bl * NL2;
        int base = bl * NL1;               // bit index of (bl, j=0): 0 or 38
        w0i  = base >> 5;                  // 0 or 1
        offi = base & 31;                  // 0 or 6
        w2v  = (const float4*)&w2sh[k * W2STRIDE];
        size_t o = (size_t)(b0 + bl) * NL2 + k;
        pS2 = out + (size_t)2 * T_STEPS * BATCH * NL1 + o;
        pM2 = pS2 + (size_t)T_STEPS * BATCH * NL2;
    }

    // ---- x prefetch: slots 0-3 staged, steps 4-7 in regs ----
    const float* xp = x + (size_t)b0 * NIN + tid;   // valid for tid < 24
    float xn0 = 0.f, xn1 = 0.f, xn2 = 0.f, xn3 = 0.f;
    int tpre = 2 * GSTEP;
    if (isX) {
        xsh[0][tid] = xp[0];
        xsh[1][tid] = xp[stepx];
        xsh[2][tid] = xp[2 * stepx];
        xsh[3][tid] = xp[3 * stepx];
        xn0 = xp[4 * stepx];
        xn1 = xp[5 * stepx];
        xn2 = xp[6 * stepx];
        xn3 = xp[7 * stepx];
        xp += 8 * stepx;
    }
    __syncthreads();

    // one L1 step from ring slot SLOT. Serial fmaf chain — EXACT passing order.
    // All 96 producer threads execute (ballot); stores gated by isL1.
#define L1STEP(SLOT)                                                           \
        {                                                                      \
            const float4* xv_ = (const float4*)&xsh[SLOT][xoff];               \
            float4 a = xv_[0], b = xv_[1], c = xv_[2];                         \
            float cur = a.x * w1r[0];                                          \
            cur = fmaf(a.y, w1r[1], cur);                                      \
            cur = fmaf(a.z, w1r[2], cur);                                      \
            cur = fmaf(a.w, w1r[3], cur);                                      \
            cur = fmaf(b.x, w1r[4], cur);                                      \
            cur = fmaf(b.y, w1r[5], cur);                                      \
            cur = fmaf(b.z, w1r[6], cur);                                      \
            cur = fmaf(b.w, w1r[7], cur);                                      \
            cur = fmaf(c.x, w1r[8], cur);                                      \
            cur = fmaf(c.y, w1r[9], cur);                                      \
            cur = fmaf(c.z, w1r[10], cur);                                     \
            cur = fmaf(c.w, w1r[11], cur);                                     \
            float mv_ = fmaf(beta1, mem1, cur);                                \
            mv_ = fmaf(vj, spk1, mv_);                                         \
            bool pr_ = (mv_ > thr);                                            \
            float spv_ = pr_ ? 1.0f : 0.0f;                                    \
            mv_ = fmaf(-spv_, thr, mv_);                                       \
            mem1 = mv_; spk1 = spv_;                                           \
            unsigned bb_ = __ballot_sync(0xFFFFFFFFu, isL1 && pr_);            \
            if ((tid & 31) == 0) sbit[SLOT][wid] = bb_;                        \
            if (isL1) {                                                        \
                *pS1 = spv_; *pM1 = mv_;                                       \
                pS1 += step1; pM1 += step1;                                    \
            }                                                                  \
        }

    // one L2 step from ring slot SLOT: 2-word bitmask read + predicated adds.
    // Bit-exact vs fmaf(spike, w, acc) since spike is 0/1; same acc pattern.
#define L2STEP(SLOT)                                                           \
        {                                                                      \
            unsigned lo_ = sbit[SLOT][w0i];                                    \
            unsigned hi_ = sbit[SLOT][w0i + 1];                                \
            unsigned long long vb_ =                                           \
                ((((unsigned long long)hi_) << 32) | lo_) >> offi;             \
            vb_ &= 0x3FFFFFFFFFull;   /* keep bits 0..37 (pad = 0) */          \
            float acc0 = 0.0f, acc1 = 0.0f, acc2 = 0.0f, acc3 = 0.0f;          \
            _Pragma("unroll")                                                  \
            for (int q = 0; q < 10; ++q) {                                     \
                float4 w4 = w2v[q];                                            \
                acc0 = ((vb_ >> (4 * q + 0)) & 1) ? acc0 + w4.x : acc0;        \
                acc1 = ((vb_ >> (4 * q + 1)) & 1) ? acc1 + w4.y : acc1;        \
                acc2 = ((vb_ >> (4 * q + 2)) & 1) ? acc2 + w4.z : acc2;        \
                acc3 = ((vb_ >> (4 * q + 3)) & 1) ? acc3 + w4.w : acc3;        \
            }                                                                  \
            float cur2 = (acc0 + acc1) + (acc2 + acc3);                        \
            float m2_ = fmaf(beta2, mem2, cur2);                               \
            float s2_ = (m2_ > thr) ? 1.0f : 0.0f;                             \
            m2_ = fmaf(-s2_, thr, m2_);                                        \
            mem2 = m2_;                                                        \
            *pS2 = s2_; *pM2 = m2_;                                            \
            pS2 += step2; pM2 += step2;                                        \
        }

#define L1ROUND(BASE)                                                          \
        if (isP) {                                                             \
            L1STEP(BASE + 0) L1STEP(BASE + 1) L1STEP(BASE + 2) L1STEP(BASE + 3)\
        }                                                                      \
        if (isX) {                                                             \
            xsh[(BASE ^ 4) + 0][tid] = xn0;                                    \
            xsh[(BASE ^ 4) + 1][tid] = xn1;                                    \
            xsh[(BASE ^ 4) + 2][tid] = xn2;                                    \
            xsh[(BASE ^ 4) + 3][tid] = xn3;                                    \
            if (tpre < T_STEPS) {                                              \
                xn0 = xp[0];                                                   \
                xn1 = xp[stepx];                                               \
                xn2 = xp[2 * stepx];                                           \
                xn3 = xp[3 * stepx];                                           \
                xp += 4 * stepx;                                               \
            }                                                                  \
            tpre += GSTEP;                                                     \
        }

#define L2ROUND(BASE)                                                          \
        if (isL2) {                                                            \
            L2STEP(BASE + 0) L2STEP(BASE + 1) L2STEP(BASE + 2) L2STEP(BASE + 3)\
        }

    // round 0: L1 only
    L1ROUND(0)
    __syncthreads();

    // rounds 1..124: L1 leads, L2 trails one round (62 pairs)
    #pragma unroll 1
    for (int r = 0; r < 62; ++r) {
        L1ROUND(4) L2ROUND(0)
        __syncthreads();
        L1ROUND(0) L2ROUND(4)
        __syncthreads();
    }

    // epilogue: L2 for steps 496-499 (slot base 0)
    L2ROUND(0)

#undef L1STEP
#undef L2STEP
#undef L1ROUND
#undef L2ROUND
}

extern "C" void kernel_launch(void* const* d_in, const int* in_sizes, int n_in,
                              void* d_out, int out_size)
{
    const float* x   = (const float*)d_in[0];
    const float* W1  = (const float*)d_in[1];
    const float* V   = (const float*)d_in[2];
    const float* W2  = (const float*)d_in[3];
    const float* b1  = (const float*)d_in[4];
    const float* b2  = (const float*)d_in[5];
    const float* th  = (const float*)d_in[6];
    float* out = (float*)d_out;

    dim3 grid(BATCH / NB);   // 1024 blocks; 7 blocks/SM -> single wave
    dim3 block(NTHREADS);
    snn_scan_kernel<<<grid, block>>>(x, W1, V, W2, b1, b2, th, out);
}

// round 12
// speedup vs baseline: 1.1164x; 1.1164x over previous
#include <cuda_runtime.h>

// SimpleSNN: T=500 sequential steps, B=2048, 12 -> 38 (RLeaky) -> 7 (Leaky)
// Outputs flat: spk1[T,B,38], mem1[T,B,38], spk2[T,B,7], mem2[T,B,7]
//
// Round-batched pipeline (G=4 steps per __syncthreads), register x prefetch,
// ballot-bitmask spk1 publication, NB=4/192-thread layout (the round-10
// 167us configuration) with ONE change: all per-step 64-bit pointer
// increments are hoisted to once-per-round; in-round stores use
// compile-time immediate offsets (STG [ptr+imm]). ~25% fewer producer
// instructions; FP op order bit-identical.

#define T_STEPS  500
#define BATCH    2048
#define NIN      12
#define NL1      38
#define NL2      7
#define NB       4              // batch elements per block
#define NTHREADS 192
#define PROD_T   160            // warps 0-4 run the L1 step body (ballot)
#define L1_T     (NB*NL1)       // 152 real L1 threads
#define L2_BASE  160            // L2 warp
#define L2_T     (NB*NL2)       // 28
#define X_T      (NB*NIN)       // 48
#define W2STRIDE 44             // padded W2 row stride (conflict-free broadcast)
#define GSTEP    4              // steps per round
#define NSLOT    8              // ring depth (2 rounds)
#define STEP1    (BATCH*NL1)    // element stride between steps, layer-1 outputs
#define STEP2    (BATCH*NL2)    // element stride between steps, layer-2 outputs

__global__ __launch_bounds__(NTHREADS, 4)
void snn_scan_kernel(const float* __restrict__ x,
                     const float* __restrict__ W1,
                     const float* __restrict__ V,
                     const float* __restrict__ W2,
                     const float* __restrict__ pb1,
                     const float* __restrict__ pb2,
                     const float* __restrict__ pth,
                     float* __restrict__ out)
{
    __shared__ float    xsh[NSLOT][X_T];   // x ring: one slot per step
    __shared__ unsigned sbit[NSLOT][8];    // spike bitmask ring: 5 words/slot
    __shared__ float    w2sh[NL2 * W2STRIDE];

    const int tid  = threadIdx.x;
    const int wid  = tid >> 5;
    const int b0   = blockIdx.x * NB;
    const float thr = *pth;

    const size_t stepx = (size_t)BATCH * NIN;

    // ---- one-time shared init ----
    for (int i = tid; i < NL2 * W2STRIDE; i += NTHREADS) {
        int k = i / W2STRIDE;
        int j = i - k * W2STRIDE;
        w2sh[i] = (j < NL1) ? W2[k * NL1 + j] : 0.0f;
    }

    const bool isP  = (tid < PROD_T);   // runs L1 step body (incl. ballot)
    const bool isL1 = (tid < L1_T);     // real L1 neuron
    const bool isX  = (tid < X_T);
    const bool isL2 = (tid >= L2_BASE) && (tid < L2_BASE + L2_T);

    // ---- layer 1 per-thread state ----
    const float beta1 = *pb1;
    float w1r[NIN];
    float vj = 0.f, mem1 = 0.f, spk1 = 0.f;
    int xoff = 0;
    float *pS1 = out, *pM1 = out;
    if (isL1) {
        int bl = tid / NL1, j = tid - bl * NL1;
        #pragma unroll
        for (int i = 0; i < NIN; ++i) w1r[i] = W1[j * NIN + i];
        vj   = V[j];
        xoff = bl * NIN;
        size_t o = (size_t)(b0 + bl) * NL1 + j;
        pS1 = out + o;
        pM1 = out + (size_t)T_STEPS * BATCH * NL1 + o;
    } else {
        #pragma unroll
        for (int i = 0; i < NIN; ++i) w1r[i] = 0.f;  // ballast lanes: defined math
    }

    // ---- layer 2 per-thread state ----
    const float beta2 = *pb2;
    float mem2 = 0.f;
    int w0i = 0, offi = 0;
    const float4* w2v = (const float4*)w2sh;
    float *pS2 = out, *pM2 = out;
    if (isL2) {
        int t2 = tid - L2_BASE;
        int bl = t2 / NL2, k = t2 - bl * NL2;
        int base = bl * NL1;               // bit index of (bl, j=0)
        w0i  = base >> 5;                  // 0..3
        offi = base & 31;
        w2v  = (const float4*)&w2sh[k * W2STRIDE];
        size_t o = (size_t)(b0 + bl) * NL2 + k;
        pS2 = out + (size_t)2 * T_STEPS * BATCH * NL1 + o;
        pM2 = pS2 + (size_t)T_STEPS * BATCH * NL2;
    }

    // ---- x prefetch: slots 0-3 staged, steps 4-7 in regs ----
    const float* xp = x + (size_t)b0 * NIN + tid;   // valid for tid < 48
    float xn0 = 0.f, xn1 = 0.f, xn2 = 0.f, xn3 = 0.f;
    int tpre = 2 * GSTEP;
    if (isX) {
        xsh[0][tid] = xp[0];
        xsh[1][tid] = xp[stepx];
        xsh[2][tid] = xp[2 * stepx];
        xsh[3][tid] = xp[3 * stepx];
        xn0 = xp[4 * stepx];
        xn1 = xp[5 * stepx];
        xn2 = xp[6 * stepx];
        xn3 = xp[7 * stepx];
        xp += 8 * stepx;
    }
    __syncthreads();

    // one L1 step from ring slot SLOT, in-round step index S (0..3).
    // Stores via immediate offsets off pS1/pM1; pointers bumped per round.
    // Serial fmaf chain — EXACT passing order.
#define L1STEP(SLOT, S)                                                        \
        {                                                                      \
            const float4* xv_ = (const float4*)&xsh[SLOT][xoff];               \
            float4 a = xv_[0], b = xv_[1], c = xv_[2];                         \
            float cur = a.x * w1r[0];                                          \
            cur = fmaf(a.y, w1r[1], cur);                                      \
            cur = fmaf(a.z, w1r[2], cur);                                      \
            cur = fmaf(a.w, w1r[3], cur);                                      \
            cur = fmaf(b.x, w1r[4], cur);                                      \
            cur = fmaf(b.y, w1r[5], cur);                                      \
            cur = fmaf(b.z, w1r[6], cur);                                      \
            cur = fmaf(b.w, w1r[7], cur);                                      \
            cur = fmaf(c.x, w1r[8], cur);                                      \
            cur = fmaf(c.y, w1r[9], cur);                                      \
            cur = fmaf(c.z, w1r[10], cur);                                     \
            cur = fmaf(c.w, w1r[11], cur);                                     \
            float mv_ = fmaf(beta1, mem1, cur);                                \
            mv_ = fmaf(vj, spk1, mv_);                                         \
            bool pr_ = (mv_ > thr);                                            \
            float spv_ = pr_ ? 1.0f : 0.0f;                                    \
            mv_ = fmaf(-spv_, thr, mv_);                                       \
            mem1 = mv_; spk1 = spv_;                                           \
            unsigned bb_ = __ballot_sync(0xFFFFFFFFu, isL1 && pr_);            \
            if ((tid & 31) == 0) sbit[SLOT][wid] = bb_;                        \
            if (isL1) {                                                        \
                pS1[(S) * STEP1] = spv_;                                       \
                pM1[(S) * STEP1] = mv_;                                        \
            }                                                                  \
        }

    // one L2 step from ring slot SLOT, in-round step index S (0..3).
    // 2-word bitmask read + predicated adds (bit-exact vs fmaf with 0/1).
#define L2STEP(SLOT, S)                                                        \
        {                                                                      \
            unsigned lo_ = sbit[SLOT][w0i];                                    \
            unsigned hi_ = sbit[SLOT][w0i + 1];                                \
            unsigned long long vb_ =                                           \
                ((((unsigned long long)hi_) << 32) | lo_) >> offi;             \
            vb_ &= 0x3FFFFFFFFFull;   /* keep bits 0..37 (pad = 0) */          \
            float acc0 = 0.0f, acc1 = 0.0f, acc2 = 0.0f, acc3 = 0.0f;          \
            _Pragma("unroll")                                                  \
            for (int q = 0; q < 10; ++q) {                                     \
                float4 w4 = w2v[q];                                            \
                acc0 = ((vb_ >> (4 * q + 0)) & 1) ? acc0 + w4.x : acc0;        \
                acc1 = ((vb_ >> (4 * q + 1)) & 1) ? acc1 + w4.y : acc1;        \
                acc2 = ((vb_ >> (4 * q + 2)) & 1) ? acc2 + w4.z : acc2;        \
                acc3 = ((vb_ >> (4 * q + 3)) & 1) ? acc3 + w4.w : acc3;        \
            }                                                                  \
            float cur2 = (acc0 + acc1) + (acc2 + acc3);                        \
            float m2_ = fmaf(beta2, mem2, cur2);                               \
            float s2_ = (m2_ > thr) ? 1.0f : 0.0f;                             \
            m2_ = fmaf(-s2_, thr, m2_);                                        \
            mem2 = m2_;                                                        \
            pS2[(S) * STEP2] = s2_;                                            \
            pM2[(S) * STEP2] = m2_;                                            \
        }

#define L1ROUND(BASE)                                                          \
        if (isP) {                                                             \
            L1STEP(BASE + 0, 0) L1STEP(BASE + 1, 1)                            \
            L1STEP(BASE + 2, 2) L1STEP(BASE + 3, 3)                            \
            if (isL1) { pS1 += 4 * STEP1; pM1 += 4 * STEP1; }                  \
        }                                                                      \
        if (isX) {                                                             \
            xsh[(BASE ^ 4) + 0][tid] = xn0;                                    \
            xsh[(BASE ^ 4) + 1][tid] = xn1;                                    \
            xsh[(BASE ^ 4) + 2][tid] = xn2;                                    \
            xsh[(BASE ^ 4) + 3][tid] = xn3;                                    \
            if (tpre < T_STEPS) {                                              \
                xn0 = xp[0];                                                   \
                xn1 = xp[stepx];                                               \
                xn2 = xp[2 * stepx];                                           \
                xn3 = xp[3 * stepx];                                           \
                xp += 4 * stepx;                                               \
            }                                                                  \
            tpre += GSTEP;                                                     \
        }

#define L2ROUND(BASE)                                                          \
        if (isL2) {                                                            \
            L2STEP(BASE + 0, 0) L2STEP(BASE + 1, 1)                            \
            L2STEP(BASE + 2, 2) L2STEP(BASE + 3, 3)                            \
            pS2 += 4 * STEP2; pM2 += 4 * STEP2;                                \
        }

    // round 0: L1 only
    L1ROUND(0)
    __syncthreads();

    // rounds 1..124: L1 leads, L2 trails one round (62 pairs)
    #pragma unroll 1
    for (int r = 0; r < 62; ++r) {
        L1ROUND(4) L2ROUND(0)
        __syncthreads();
        L1ROUND(0) L2ROUND(4)
        __syncthreads();
    }

    // epilogue: L2 for steps 496-499 (slot base 0)
    L2ROUND(0)

#undef L1STEP
#undef L2STEP
#undef L1ROUND
#undef L2ROUND
}

extern "C" void kernel_launch(void* const* d_in, const int* in_sizes, int n_in,
                              void* d_out, int out_size)
{
    const float* x   = (const float*)d_in[0];
    const float* W1  = (const float*)d_in[1];
    const float* V   = (const float*)d_in[2];
    const float* W2  = (const float*)d_in[3];
    const float* b1  = (const float*)d_in[4];
    const float* b2  = (const float*)d_in[5];
    const float* th  = (const float*)d_in[6];
    float* out = (float*)d_out;

    dim3 grid(BATCH / NB);   // 512 blocks; 4 blocks/SM -> single wave
    dim3 block(NTHREADS);
    snn_scan_kernel<<<grid, block>>>(x, W1, V, W2, b1, b2, th, out);
}

// round 13
// speedup vs baseline: 1.3755x; 1.2321x over previous
#include <cuda_runtime.h>

// SimpleSNN: T=500 sequential steps, B=2048, 12 -> 38 (RLeaky) -> 7 (Leaky)
// Outputs flat: spk1[T,B,38], mem1[T,B,38], spk2[T,B,7], mem2[T,B,7]
//
// Round-batched pipeline, G=10 steps per __syncthreads (50 barriers total).
// Register x prefetch spread over 96 stager threads (5 regs each, no
// cp.async), ballot-bitmask spk1, immediate-offset stores (round-12 body).
// FP op order bit-identical to all passing rounds.

#define T_STEPS  500
#define BATCH    2048
#define NIN      12
#define NL1      38
#define NL2      7
#define NB       4              // batch elements per block
#define NTHREADS 192
#define PROD_T   160            // warps 0-4 run the L1 step body (ballot)
#define L1_T     (NB*NL1)       // 152 real L1 threads
#define L2_BASE  160            // L2 warp
#define L2_T     (NB*NL2)       // 28
#define X_T      (NB*NIN)       // 48 x elements per step
#define STAGE_T  96             // stager threads (2 groups of 48)
#define W2STRIDE 44             // padded W2 row stride
#define G        10             // steps per round (500 = 50 rounds)
#define NSLOT    (2*G)          // ring depth (2 rounds)
#define STEP1    (BATCH*NL1)    // element stride between steps, layer-1 outputs
#define STEP2    (BATCH*NL2)    // element stride between steps, layer-2 outputs

__global__ __launch_bounds__(NTHREADS, 4)
void snn_scan_kernel(const float* __restrict__ x,
                     const float* __restrict__ W1,
                     const float* __restrict__ V,
                     const float* __restrict__ W2,
                     const float* __restrict__ pb1,
                     const float* __restrict__ pb2,
                     const float* __restrict__ pth,
                     float* __restrict__ out)
{
    __shared__ float    xsh[NSLOT][X_T];   // x ring: one slot per step
    __shared__ unsigned sbit[NSLOT][8];    // spike bitmask ring: 5 words/slot
    __shared__ float    w2sh[NL2 * W2STRIDE];

    const int tid  = threadIdx.x;
    const int wid  = tid >> 5;
    const int b0   = blockIdx.x * NB;
    const float thr = *pth;

    const size_t stepx = (size_t)BATCH * NIN;

    // ---- one-time shared init ----
    for (int i = tid; i < NL2 * W2STRIDE; i += NTHREADS) {
        int k = i / W2STRIDE;
        int j = i - k * W2STRIDE;
        w2sh[i] = (j < NL1) ? W2[k * NL1 + j] : 0.0f;
    }

    const bool isP  = (tid < PROD_T);    // runs L1 step body (incl. ballot)
    const bool isL1 = (tid < L1_T);      // real L1 neuron
    const bool isS  = (tid < STAGE_T);   // x stager (also an L1 thread)
    const bool isL2 = (tid >= L2_BASE) && (tid < L2_BASE + L2_T);

    // ---- layer 1 per-thread state ----
    const float beta1 = *pb1;
    float w1r[NIN];
    float vj = 0.f, mem1 = 0.f, spk1 = 0.f;
    int xoff = 0;
    float *pS1 = out, *pM1 = out;
    if (isL1) {
        int bl = tid / NL1, j = tid - bl * NL1;
        #pragma unroll
        for (int i = 0; i < NIN; ++i) w1r[i] = W1[j * NIN + i];
        vj   = V[j];
        xoff = bl * NIN;
        size_t o = (size_t)(b0 + bl) * NL1 + j;
        pS1 = out + o;
        pM1 = out + (size_t)T_STEPS * BATCH * NL1 + o;
    } else {
        #pragma unroll
        for (int i = 0; i < NIN; ++i) w1r[i] = 0.f;  // ballast lanes: defined math
    }

    // ---- layer 2 per-thread state ----
    const float beta2 = *pb2;
    float mem2 = 0.f;
    int w0i = 0, offi = 0;
    const float4* w2v = (const float4*)w2sh;
    float *pS2 = out, *pM2 = out;
    if (isL2) {
        int t2 = tid - L2_BASE;
        int bl = t2 / NL2, k = t2 - bl * NL2;
        int base = bl * NL1;               // bit index of (bl, j=0)
        w0i  = base >> 5;                  // 0..3
        offi = base & 31;
        w2v  = (const float4*)&w2sh[k * W2STRIDE];
        size_t o = (size_t)(b0 + bl) * NL2 + k;
        pS2 = out + (size_t)2 * T_STEPS * BATCH * NL1 + o;
        pM2 = pS2 + (size_t)T_STEPS * BATCH * NL2;
    }

    // ---- x staging: stager tid<96 owns element u=tid%48 for 5 steps/round ----
    // group g = tid/48: handles relative steps 5g..5g+4 of each round.
    const int su = tid % 48;
    const int sg = tid / 48;               // 0 or 1 (for tid<96)
    float xn[5] = {0.f, 0.f, 0.f, 0.f, 0.f};
    const float* xq = x;                   // running prefetch pointer
    int tpre = 2 * G;                      // step-base of next prefetch
    if (isS) {
        const float* xb = x + (size_t)b0 * NIN + su;
        // stage round 0 (steps 0-9) directly into slots
        #pragma unroll
        for (int i = 0; i < 5; ++i)
            xsh[5 * sg + i][su] = xb[(size_t)(5 * sg + i) * stepx];
        // hold round 1 (steps 10-19) in regs
        #pragma unroll
        for (int i = 0; i < 5; ++i)
            xn[i] = xb[(size_t)(G + 5 * sg + i) * stepx];
        xq = xb + (size_t)(2 * G + 5 * sg) * stepx;
    }
    __syncthreads();

    // one L1 step from ring slot SLOT, in-round step index S (0..9).
    // Serial fmaf chain — EXACT passing order. Imm-offset stores.
#define L1STEP(SLOT, S)                                                        \
        {                                                                      \
            const float4* xv_ = (const float4*)&xsh[SLOT][xoff];               \
            float4 a = xv_[0], b = xv_[1], c = xv_[2];                         \
            float cur = a.x * w1r[0];                                          \
            cur = fmaf(a.y, w1r[1], cur);                                      \
            cur = fmaf(a.z, w1r[2], cur);                                      \
            cur = fmaf(a.w, w1r[3], cur);                                      \
            cur = fmaf(b.x, w1r[4], cur);                                      \
            cur = fmaf(b.y, w1r[5], cur);                                      \
            cur = fmaf(b.z, w1r[6], cur);                                      \
            cur = fmaf(b.w, w1r[7], cur);                                      \
            cur = fmaf(c.x, w1r[8], cur);                                      \
            cur = fmaf(c.y, w1r[9], cur);                                      \
            cur = fmaf(c.z, w1r[10], cur);                                     \
            cur = fmaf(c.w, w1r[11], cur);                                     \
            float mv_ = fmaf(beta1, mem1, cur);                                \
            mv_ = fmaf(vj, spk1, mv_);                                         \
            bool pr_ = (mv_ > thr);                                            \
            float spv_ = pr_ ? 1.0f : 0.0f;                                    \
            mv_ = fmaf(-spv_, thr, mv_);                                       \
            mem1 = mv_; spk1 = spv_;                                           \
            unsigned bb_ = __ballot_sync(0xFFFFFFFFu, isL1 && pr_);            \
            if ((tid & 31) == 0) sbit[SLOT][wid] = bb_;                        \
            if (isL1) {                                                        \
                pS1[(S) * STEP1] = spv_;                                       \
                pM1[(S) * STEP1] = mv_;                                        \
            }                                                                  \
        }

    // one L2 step from ring slot SLOT, in-round step index S (0..9).
    // 2-word bitmask read + predicated adds (bit-exact vs fmaf with 0/1).
#define L2STEP(SLOT, S)                                                        \
        {                                                                      \
            unsigned lo_ = sbit[SLOT][w0i];                                    \
            unsigned hi_ = sbit[SLOT][w0i + 1];                                \
            unsigned long long vb_ =                                           \
                ((((unsigned long long)hi_) << 32) | lo_) >> offi;             \
            vb_ &= 0x3FFFFFFFFFull;   /* keep bits 0..37 (pad = 0) */          \
            float acc0 = 0.0f, acc1 = 0.0f, acc2 = 0.0f, acc3 = 0.0f;          \
            _Pragma("unroll")                                                  \
            for (int q = 0; q < 10; ++q) {                                     \
                float4 w4 = w2v[q];                                            \
                acc0 = ((vb_ >> (4 * q + 0)) & 1) ? acc0 + w4.x : acc0;        \
                acc1 = ((vb_ >> (4 * q + 1)) & 1) ? acc1 + w4.y : acc1;        \
                acc2 = ((vb_ >> (4 * q + 2)) & 1) ? acc2 + w4.z : acc2;        \
                acc3 = ((vb_ >> (4 * q + 3)) & 1) ? acc3 + w4.w : acc3;        \
            }                                                                  \
            float cur2 = (acc0 + acc1) + (acc2 + acc3);                        \
            float m2_ = fmaf(beta2, mem2, cur2);                               \
            float s2_ = (m2_ > thr) ? 1.0f : 0.0f;                             \
            m2_ = fmaf(-s2_, thr, m2_);                                        \
            mem2 = m2_;                                                        \
            pS2[(S) * STEP2] = s2_;                                            \
            pM2[(S) * STEP2] = m2_;                                            \
        }

    // L1 round at ring half BASE (0 or G): run 10 L1 steps, then stagers
    // write held regs to the other half and prefetch the round after.
#define L1ROUND(BASE)                                                          \
        if (isP) {                                                             \
            L1STEP((BASE) + 0, 0) L1STEP((BASE) + 1, 1)                        \
            L1STEP((BASE) + 2, 2) L1STEP((BASE) + 3, 3)                        \
            L1STEP((BASE) + 4, 4) L1STEP((BASE) + 5, 5)                        \
            L1STEP((BASE) + 6, 6) L1STEP((BASE) + 7, 7)                        \
            L1STEP((BASE) + 8, 8) L1STEP((BASE) + 9, 9)                        \
            if (isL1) { pS1 += G * STEP1; pM1 += G * STEP1; }                  \
        }                                                                      \
        if (isS) {                                                             \
            _Pragma("unroll")                                                  \
            for (int i = 0; i < 5; ++i)                                        \
                xsh[((BASE) ^ G) + 5 * sg + i][su] = xn[i];                    \
            if (tpre < T_STEPS) {                                              \
                _Pragma("unroll")                                              \
                for (int i = 0; i < 5; ++i)                                    \
                    xn[i] = xq[(size_t)i * stepx];                             \
                xq += (size_t)G * stepx;                                       \
            }                                                                  \
        }                                                                      \
        tpre += G;

#define L2ROUND(BASE)                                                          \
        if (isL2) {                                                            \
            L2STEP((BASE) + 0, 0) L2STEP((BASE) + 1, 1)                        \
            L2STEP((BASE) + 2, 2) L2STEP((BASE) + 3, 3)                        \
            L2STEP((BASE) + 4, 4) L2STEP((BASE) + 5, 5)                        \
            L2STEP((BASE) + 6, 6) L2STEP((BASE) + 7, 7)                        \
            L2STEP((BASE) + 8, 8) L2STEP((BASE) + 9, 9)                        \
            pS2 += G * STEP2; pM2 += G * STEP2;                                \
        }

    // round 0: L1 only (steps 0-9; stages 10-19; prefetches 20-29)
    L1ROUND(0)
    __syncthreads();

    // rounds 1..48: L1 leads, L2 trails one round (24 pairs)
    #pragma unroll 1
    for (int r = 0; r < 24; ++r) {
        L1ROUND(G) L2ROUND(0)
        __syncthreads();
        L1ROUND(0) L2ROUND(G)
        __syncthreads();
    }

    // round 49: L1 steps 490-499 (half G), L2 steps 480-489 (half 0)
    L1ROUND(G) L2ROUND(0)
    __syncthreads();

    // epilogue: L2 steps 490-499 (half G)
    L2ROUND(G)

#undef L1STEP
#undef L2STEP
#undef L1ROUND
#undef L2ROUND
}

extern "C" void kernel_launch(void* const* d_in, const int* in_sizes, int n_in,
                              void* d_out, int out_size)
{
    const float* x   = (const float*)d_in[0];
    const float* W1  = (const float*)d_in[1];
    const float* V   = (const float*)d_in[2];
    const float* W2  = (const float*)d_in[3];
    const float* b1  = (const float*)d_in[4];
    const float* b2  = (const float*)d_in[5];
    const float* th  = (const float*)d_in[6];
    float* out = (float*)d_out;

    dim3 grid(BATCH / NB);   // 512 blocks; 4 blocks/SM -> single wave
    dim3 block(NTHREADS);
    snn_scan_kernel<<<grid, block>>>(x, W1, V, W2, b1, b2, th, out);
}

// round 14
// speedup vs baseline: 1.7556x; 1.2763x over previous
#include <cuda_runtime.h>

// SimpleSNN: T=500 sequential steps, B=2048, 12 -> 38 (RLeaky) -> 7 (Leaky)
// Outputs flat: spk1[T,B,38], mem1[T,B,38], spk2[T,B,7], mem2[T,B,7]
//
// Round-batched pipeline, G=20 steps per __syncthreads (26 barriers total).
// Register x prefetch spread over 96 stager threads (10 regs each),
// ballot-bitmask spk1, immediate-offset stores.
// FP op order bit-identical to all passing rounds.

#define T_STEPS  500
#define BATCH    2048
#define NIN      12
#define NL1      38
#define NL2      7
#define NB       4              // batch elements per block
#define NTHREADS 192
#define PROD_T   160            // warps 0-4 run the L1 step body (ballot)
#define L1_T     (NB*NL1)       // 152 real L1 threads
#define L2_BASE  160            // L2 warp
#define L2_T     (NB*NL2)       // 28
#define X_T      (NB*NIN)       // 48 x elements per step
#define STAGE_T  96             // stager threads (2 groups of 48)
#define HSTEP    10             // steps staged per stager thread (G/2)
#define W2STRIDE 44             // padded W2 row stride
#define G        20             // steps per round (500 = 25 rounds)
#define NSLOT    (2*G)          // ring depth (2 rounds)
#define STEP1    (BATCH*NL1)    // element stride between steps, layer-1 outputs
#define STEP2    (BATCH*NL2)    // element stride between steps, layer-2 outputs

__global__ __launch_bounds__(NTHREADS, 4)
void snn_scan_kernel(const float* __restrict__ x,
                     const float* __restrict__ W1,
                     const float* __restrict__ V,
                     const float* __restrict__ W2,
                     const float* __restrict__ pb1,
                     const float* __restrict__ pb2,
                     const float* __restrict__ pth,
                     float* __restrict__ out)
{
    __shared__ float    xsh[NSLOT][X_T];   // x ring: one slot per step
    __shared__ unsigned sbit[NSLOT][8];    // spike bitmask ring: 5 words/slot
    __shared__ float    w2sh[NL2 * W2STRIDE];

    const int tid  = threadIdx.x;
    const int wid  = tid >> 5;
    const int b0   = blockIdx.x * NB;
    const float thr = *pth;

    const size_t stepx = (size_t)BATCH * NIN;

    // ---- one-time shared init ----
    for (int i = tid; i < NL2 * W2STRIDE; i += NTHREADS) {
        int k = i / W2STRIDE;
        int j = i - k * W2STRIDE;
        w2sh[i] = (j < NL1) ? W2[k * NL1 + j] : 0.0f;
    }

    const bool isP  = (tid < PROD_T);    // runs L1 step body (incl. ballot)
    const bool isL1 = (tid < L1_T);      // real L1 neuron
    const bool isS  = (tid < STAGE_T);   // x stager (also an L1 thread)
    const bool isL2 = (tid >= L2_BASE) && (tid < L2_BASE + L2_T);

    // ---- layer 1 per-thread state ----
    const float beta1 = *pb1;
    float w1r[NIN];
    float vj = 0.f, mem1 = 0.f, spk1 = 0.f;
    int xoff = 0;
    float *pS1 = out, *pM1 = out;
    if (isL1) {
        int bl = tid / NL1, j = tid - bl * NL1;
        #pragma unroll
        for (int i = 0; i < NIN; ++i) w1r[i] = W1[j * NIN + i];
        vj   = V[j];
        xoff = bl * NIN;
        size_t o = (size_t)(b0 + bl) * NL1 + j;
        pS1 = out + o;
        pM1 = out + (size_t)T_STEPS * BATCH * NL1 + o;
    } else {
        #pragma unroll
        for (int i = 0; i < NIN; ++i) w1r[i] = 0.f;  // ballast lanes: defined math
    }

    // ---- layer 2 per-thread state ----
    const float beta2 = *pb2;
    float mem2 = 0.f;
    int w0i = 0, offi = 0;
    const float4* w2v = (const float4*)w2sh;
    float *pS2 = out, *pM2 = out;
    if (isL2) {
        int t2 = tid - L2_BASE;
        int bl = t2 / NL2, k = t2 - bl * NL2;
        int base = bl * NL1;               // bit index of (bl, j=0)
        w0i  = base >> 5;                  // 0..3
        offi = base & 31;
        w2v  = (const float4*)&w2sh[k * W2STRIDE];
        size_t o = (size_t)(b0 + bl) * NL2 + k;
        pS2 = out + (size_t)2 * T_STEPS * BATCH * NL1 + o;
        pM2 = pS2 + (size_t)T_STEPS * BATCH * NL2;
    }

    // ---- x staging: stager tid<96 owns element u=tid%48 for 10 steps/round ----
    // group g = tid/48: handles relative steps 10g..10g+9 of each round.
    const int su = tid % 48;
    const int sg = tid / 48;               // 0 or 1 (for tid<96)
    float xn[HSTEP];
    #pragma unroll
    for (int i = 0; i < HSTEP; ++i) xn[i] = 0.f;
    const float* xq = x;                   // running prefetch pointer
    int tpre = 2 * G;                      // step-base of next prefetch
    if (isS) {
        const float* xb = x + (size_t)b0 * NIN + su;
        // stage round 0 (steps 0-19) directly into slots
        #pragma unroll
        for (int i = 0; i < HSTEP; ++i)
            xsh[HSTEP * sg + i][su] = xb[(size_t)(HSTEP * sg + i) * stepx];
        // hold round 1 (steps 20-39) in regs
        #pragma unroll
        for (int i = 0; i < HSTEP; ++i)
            xn[i] = xb[(size_t)(G + HSTEP * sg + i) * stepx];
        xq = xb + (size_t)(2 * G + HSTEP * sg) * stepx;
    }
    __syncthreads();

    // one L1 step from ring slot SLOT, in-round step index S (0..G-1).
    // Serial fmaf chain — EXACT passing order. Imm-offset stores.
#define L1STEP(SLOT, S)                                                        \
        {                                                                      \
            const float4* xv_ = (const float4*)&xsh[SLOT][xoff];               \
            float4 a = xv_[0], b = xv_[1], c = xv_[2];                         \
            float cur = a.x * w1r[0];                                          \
            cur = fmaf(a.y, w1r[1], cur);                                      \
            cur = fmaf(a.z, w1r[2], cur);                                      \
            cur = fmaf(a.w, w1r[3], cur);                                      \
            cur = fmaf(b.x, w1r[4], cur);                                      \
            cur = fmaf(b.y, w1r[5], cur);                                      \
            cur = fmaf(b.z, w1r[6], cur);                                      \
            cur = fmaf(b.w, w1r[7], cur);                                      \
            cur = fmaf(c.x, w1r[8], cur);                                      \
            cur = fmaf(c.y, w1r[9], cur);                                      \
            cur = fmaf(c.z, w1r[10], cur);                                     \
            cur = fmaf(c.w, w1r[11], cur);                                     \
            float mv_ = fmaf(beta1, mem1, cur);                                \
            mv_ = fmaf(vj, spk1, mv_);                                         \
            bool pr_ = (mv_ > thr);                                            \
            float spv_ = pr_ ? 1.0f : 0.0f;                                    \
            mv_ = fmaf(-spv_, thr, mv_);                                       \
            mem1 = mv_; spk1 = spv_;                                           \
            unsigned bb_ = __ballot_sync(0xFFFFFFFFu, isL1 && pr_);            \
            if ((tid & 31) == 0) sbit[SLOT][wid] = bb_;                        \
            if (isL1) {                                                        \
                pS1[(S) * STEP1] = spv_;                                       \
                pM1[(S) * STEP1] = mv_;                                        \
            }                                                                  \
        }

    // one L2 step from ring slot SLOT, in-round step index S (0..G-1).
    // 2-word bitmask read + predicated adds (bit-exact vs fmaf with 0/1).
#define L2STEP(SLOT, S)                                                        \
        {                                                                      \
            unsigned lo_ = sbit[SLOT][w0i];                                    \
            unsigned hi_ = sbit[SLOT][w0i + 1];                                \
            unsigned long long vb_ =                                           \
                ((((unsigned long long)hi_) << 32) | lo_) >> offi;             \
            vb_ &= 0x3FFFFFFFFFull;   /* keep bits 0..37 (pad = 0) */          \
            float acc0 = 0.0f, acc1 = 0.0f, acc2 = 0.0f, acc3 = 0.0f;          \
            _Pragma("unroll")                                                  \
            for (int q = 0; q < 10; ++q) {                                     \
                float4 w4 = w2v[q];                                            \
                acc0 = ((vb_ >> (4 * q + 0)) & 1) ? acc0 + w4.x : acc0;        \
                acc1 = ((vb_ >> (4 * q + 1)) & 1) ? acc1 + w4.y : acc1;        \
                acc2 = ((vb_ >> (4 * q + 2)) & 1) ? acc2 + w4.z : acc2;        \
                acc3 = ((vb_ >> (4 * q + 3)) & 1) ? acc3 + w4.w : acc3;        \
            }                                                                  \
            float cur2 = (acc0 + acc1) + (acc2 + acc3);                        \
            float m2_ = fmaf(beta2, mem2, cur2);                               \
            float s2_ = (m2_ > thr) ? 1.0f : 0.0f;                             \
            m2_ = fmaf(-s2_, thr, m2_);                                        \
            mem2 = m2_;                                                        \
            pS2[(S) * STEP2] = s2_;                                            \
            pM2[(S) * STEP2] = m2_;                                            \
        }

    // L1 round at ring half BASE (0 or G): run G L1 steps, then stagers
    // write held regs to the other half and prefetch the round after.
#define L1ROUND(BASE)                                                          \
        if (isP) {                                                             \
            _Pragma("unroll")                                                  \
            for (int ls = 0; ls < G; ++ls)                                     \
                L1STEP((BASE) + ls, ls)                                        \
            if (isL1) { pS1 += G * STEP1; pM1 += G * STEP1; }                  \
        }                                                                      \
        if (isS) {                                                             \
            _Pragma("unroll")                                                  \
            for (int i = 0; i < HSTEP; ++i)                                    \
                xsh[((BASE) ^ G) + HSTEP * sg + i][su] = xn[i];                \
            if (tpre < T_STEPS) {                                              \
                _Pragma("unroll")                                              \
                for (int i = 0; i < HSTEP; ++i)                                \
                    xn[i] = xq[(size_t)i * stepx];                             \
                xq += (size_t)G * stepx;                                       \
            }                                                                  \
        }                                                                      \
        tpre += G;

#define L2ROUND(BASE)                                                          \
        if (isL2) {                                                            \
            _Pragma("unroll")                                                  \
            for (int ks = 0; ks < G; ++ks)                                     \
                L2STEP((BASE) + ks, ks)                                        \
            pS2 += G * STEP2; pM2 += G * STEP2;                                \
        }

    // round 0: L1 only (steps 0-19; stages 20-39; prefetches 40-59)
    L1ROUND(0)
    __syncthreads();

    // rounds 1..24: L1 leads, L2 trails one round (12 pairs)
    #pragma unroll 1
    for (int r = 0; r < 12; ++r) {
        L1ROUND(G) L2ROUND(0)
        __syncthreads();
        L1ROUND(0) L2ROUND(G)
        __syncthreads();
    }

    // epilogue: L2 for steps 480-499 (half 0)
    L2ROUND(0)

#undef L1STEP
#undef L2STEP
#undef L1ROUND
#undef L2ROUND
}

extern "C" void kernel_launch(void* const* d_in, const int* in_sizes, int n_in,
                              void* d_out, int out_size)
{
    const float* x   = (const float*)d_in[0];
    const float* W1  = (const float*)d_in[1];
    const float* V   = (const float*)d_in[2];
    const float* W2  = (const float*)d_in[3];
    const float* b1  = (const float*)d_in[4];
    const float* b2  = (const float*)d_in[5];
    const float* th  = (const float*)d_in[6];
    float* out = (float*)d_out;

    dim3 grid(BATCH / NB);   // 512 blocks; 4 blocks/SM -> single wave
    dim3 block(NTHREADS);
    snn_scan_kernel<<<grid, block>>>(x, W1, V, W2, b1, b2, th, out);
}